// round 1
// baseline (speedup 1.0000x reference)
#include <cuda_runtime.h>
#include <cstdint>

// Problem constants
#define B_Q   256
#define DIM   512
#define N_MEM 500000
#define TOPK  5

// Tiling
#define BN         64
#define KC         16
#define NCHUNK     (DIM / KC)            // 32
#define SPLIT_ROWS 512
#define TILES      (SPLIT_ROWS / BN)     // 8
#define NSPLIT     ((N_MEM + SPLIT_ROWS - 1) / SPLIT_ROWS)  // 977

// Dynamic smem layout (floats):
//  As: KC*256 = 4096 | Bs: KC*64 = 1024 | ds: 256*65 = 16640 | qs: 256 | ms: 64
//  bd: 256*5 = 1280  | bi(int): 1280
#define SMEM_FLOATS (KC*256 + KC*64 + 256*65 + 256 + BN + B_Q*TOPK)
#define SMEM_BYTES  ((SMEM_FLOATS + B_Q*TOPK) * 4)   // 98560 bytes

// Scratch (device globals: no allocation allowed)
__device__ float g_msq[N_MEM];
__device__ float g_qsq[B_Q];
__device__ float g_pd[(size_t)B_Q * NSPLIT * TOPK];
__device__ int   g_pi[(size_t)B_Q * NSPLIT * TOPK];

// ---------------------------------------------------------------------------
// Row sum-of-squares: one warp per row (float4 loads, warp shuffle reduce)
// ---------------------------------------------------------------------------
__global__ void msq_kernel(const float* __restrict__ mem) {
    int w    = (blockIdx.x * blockDim.x + threadIdx.x) >> 5;
    int lane = threadIdx.x & 31;
    if (w >= N_MEM) return;
    const float4* row = (const float4*)(mem + (long)w * DIM);
    float s = 0.f;
#pragma unroll
    for (int i = 0; i < 4; i++) {
        float4 v = row[lane + 32 * i];
        s += v.x * v.x + v.y * v.y + v.z * v.z + v.w * v.w;
    }
#pragma unroll
    for (int o = 16; o > 0; o >>= 1) s += __shfl_xor_sync(0xFFFFFFFFu, s, o);
    if (lane == 0) g_msq[w] = s;
}

__global__ void qsq_kernel(const float* __restrict__ qm) {
    int w    = (blockIdx.x * blockDim.x + threadIdx.x) >> 5;
    int lane = threadIdx.x & 31;
    if (w >= B_Q) return;
    const float4* row = (const float4*)(qm + (long)w * DIM);
    float s = 0.f;
#pragma unroll
    for (int i = 0; i < 4; i++) {
        float4 v = row[lane + 32 * i];
        s += v.x * v.x + v.y * v.y + v.z * v.z + v.w * v.w;
    }
#pragma unroll
    for (int o = 16; o > 0; o >>= 1) s += __shfl_xor_sync(0xFFFFFFFFu, s, o);
    if (lane == 0) g_qsq[w] = s;
}

// ---------------------------------------------------------------------------
// Main: 256x64 distance tiles (all queries resident), fused running top-5.
// Each block owns SPLIT_ROWS memory rows; memory matrix is read from HBM once.
// ---------------------------------------------------------------------------
__global__ void __launch_bounds__(256, 1)
knn_main(const float* __restrict__ qm, const float* __restrict__ mem) {
    extern __shared__ float sm[];
    float* As = sm;                    // [KC][256]  k-major
    float* Bs = As + KC * 256;         // [KC][64]   k-major
    float* ds = Bs + KC * BN;          // [256][65]  distance tile (pitch 65)
    float* qs = ds + 256 * 65;         // [256]      ||q||^2
    float* ms = qs + 256;              // [64]       ||m||^2 for tile
    float* bd = ms + BN;               // [256][5]   running best dists
    int*   bi = (int*)(bd + B_Q * TOPK);

    const int tid = threadIdx.x;
    const int tm  = tid & 31;   // query-group lane (m)
    const int tn  = tid >> 5;   // row-group (n)

    qs[tid] = g_qsq[tid];
#pragma unroll
    for (int j = 0; j < TOPK; j++) { bd[tid * TOPK + j] = 3.0e38f; bi[tid * TOPK + j] = 0; }
    __syncthreads();

    const int splitBase = blockIdx.x * SPLIT_ROWS;
    const float4* qrow  = (const float4*)(qm + (long)tid * DIM);  // A row = query tid
    const int br = tid >> 2;        // B tile row 0..63
    const int bk = tid & 3;         // which float4 within 16-float k-chunk

    for (int tile = 0; tile < TILES; tile++) {
        const int n0     = splitBase + tile * BN;
        const int gr     = n0 + br;
        const bool bval  = (gr < N_MEM);
        const float4* mrow = (const float4*)(mem + (long)(bval ? gr : 0) * DIM);

        float acc[8][8];
#pragma unroll
        for (int i = 0; i < 8; i++)
#pragma unroll
            for (int j = 0; j < 8; j++) acc[i][j] = 0.f;

        // register prefetch of chunk 0
        float4 ra0 = qrow[0], ra1 = qrow[1], ra2 = qrow[2], ra3 = qrow[3];
        float4 rb  = bval ? mrow[bk] : make_float4(0.f, 0.f, 0.f, 0.f);

        for (int c = 0; c < NCHUNK; c++) {
            // stage current chunk into smem (transposed to k-major)
            As[0 * 256 + tid]  = ra0.x; As[1 * 256 + tid]  = ra0.y;
            As[2 * 256 + tid]  = ra0.z; As[3 * 256 + tid]  = ra0.w;
            As[4 * 256 + tid]  = ra1.x; As[5 * 256 + tid]  = ra1.y;
            As[6 * 256 + tid]  = ra1.z; As[7 * 256 + tid]  = ra1.w;
            As[8 * 256 + tid]  = ra2.x; As[9 * 256 + tid]  = ra2.y;
            As[10 * 256 + tid] = ra2.z; As[11 * 256 + tid] = ra2.w;
            As[12 * 256 + tid] = ra3.x; As[13 * 256 + tid] = ra3.y;
            As[14 * 256 + tid] = ra3.z; As[15 * 256 + tid] = ra3.w;
            Bs[(bk * 4 + 0) * BN + br] = rb.x;
            Bs[(bk * 4 + 1) * BN + br] = rb.y;
            Bs[(bk * 4 + 2) * BN + br] = rb.z;
            Bs[(bk * 4 + 3) * BN + br] = rb.w;
            __syncthreads();

            // prefetch next chunk (LDG latency hidden under FFMA block below)
            if (c + 1 < NCHUNK) {
                int k4 = (c + 1) * 4;
                ra0 = qrow[k4 + 0]; ra1 = qrow[k4 + 1];
                ra2 = qrow[k4 + 2]; ra3 = qrow[k4 + 3];
                rb  = bval ? mrow[k4 + bk] : make_float4(0.f, 0.f, 0.f, 0.f);
            }

#pragma unroll
            for (int kk = 0; kk < KC; kk++) {
                float4 A0 = *(const float4*)(As + kk * 256 + tm * 4);
                float4 A1 = *(const float4*)(As + kk * 256 + 128 + tm * 4);
                float4 B0 = *(const float4*)(Bs + kk * BN + tn * 4);
                float4 B1 = *(const float4*)(Bs + kk * BN + 32 + tn * 4);
                float av[8] = {A0.x, A0.y, A0.z, A0.w, A1.x, A1.y, A1.z, A1.w};
                float bv[8] = {B0.x, B0.y, B0.z, B0.w, B1.x, B1.y, B1.z, B1.w};
#pragma unroll
                for (int i = 0; i < 8; i++)
#pragma unroll
                    for (int j = 0; j < 8; j++)
                        acc[i][j] = fmaf(av[i], bv[j], acc[i][j]);
            }
            __syncthreads();
        }

        // tile row norms
        if (tid < BN) {
            int r = n0 + tid;
            ms[tid] = (r < N_MEM) ? g_msq[r] : 3.0e38f;
        }
        __syncthreads();

        // write squared distances into smem tile
#pragma unroll
        for (int i = 0; i < 8; i++) {
            int m = (i < 4) ? (tm * 4 + i) : (128 + tm * 4 + (i - 4));
            float qq = qs[m];
#pragma unroll
            for (int j = 0; j < 8; j++) {
                int n = (j < 4) ? (tn * 4 + j) : (32 + tn * 4 + (j - 4));
                ds[m * 65 + n] = qq + ms[n] - 2.0f * acc[i][j];
            }
        }
        __syncthreads();

        // per-query running top-5 (thread tid owns query tid)
        {
            const float* row = ds + tid * 65;
            float* bdr = bd + tid * TOPK;
            int*   bir = bi + tid * TOPK;
            for (int n = 0; n < BN; n++) {
                float dv = row[n];
                if (dv < bdr[TOPK - 1]) {
                    int p = TOPK - 1;
                    while (p > 0 && bdr[p - 1] > dv) {
                        bdr[p] = bdr[p - 1]; bir[p] = bir[p - 1]; --p;
                    }
                    bdr[p] = dv; bir[p] = n0 + n;
                }
            }
        }
        __syncthreads();
    }

    // write this split's partial top-5 per query
#pragma unroll
    for (int j = 0; j < TOPK; j++) {
        long o = ((long)tid * NSPLIT + blockIdx.x) * TOPK + j;
        g_pd[o] = bd[tid * TOPK + j];
        g_pi[o] = bi[tid * TOPK + j];
    }
}

// ---------------------------------------------------------------------------
// Merge: one warp per query over NSPLIT*5 candidates
// ---------------------------------------------------------------------------
__global__ void knn_merge(float* __restrict__ out, int out_elems) {
    const int qy   = blockIdx.x;
    const int lane = threadIdx.x;
    const int CAND = NSPLIT * TOPK;
    const float* pd = g_pd + (long)qy * CAND;
    const int*   pi = g_pi + (long)qy * CAND;

    float d[TOPK]; int ix[TOPK];
#pragma unroll
    for (int j = 0; j < TOPK; j++) { d[j] = 3.0e38f; ix[j] = 0; }

    for (int c = lane; c < CAND; c += 32) {
        float dv = pd[c];
        if (dv < d[TOPK - 1]) {
            int p = TOPK - 1;
            while (p > 0 && d[p - 1] > dv) { d[p] = d[p - 1]; ix[p] = ix[p - 1]; --p; }
            d[p] = dv; ix[p] = pi[c];
        }
    }

    __shared__ float sd[32 * TOPK];
    __shared__ int   si[32 * TOPK];
#pragma unroll
    for (int j = 0; j < TOPK; j++) { sd[lane * TOPK + j] = d[j]; si[lane * TOPK + j] = ix[j]; }
    __syncwarp();

    if (lane == 0) {
        float fd[TOPK]; int fi[TOPK];
#pragma unroll
        for (int j = 0; j < TOPK; j++) { fd[j] = 3.0e38f; fi[j] = 0; }
        for (int c = 0; c < 32 * TOPK; c++) {
            float dv = sd[c];
            if (dv < fd[TOPK - 1]) {
                int p = TOPK - 1;
                while (p > 0 && fd[p - 1] > dv) { fd[p] = fd[p - 1]; fi[p] = fi[p - 1]; --p; }
                fd[p] = dv; fi[p] = si[c];
            }
        }
#pragma unroll
        for (int j = 0; j < TOPK; j++) {
            out[qy * TOPK + j] = fd[j];                       // distances [B, K]
            if (out_elems >= 2 * B_Q * TOPK)                  // then indices [B, K] as float
                out[B_Q * TOPK + qy * TOPK + j] = (float)fi[j];
        }
    }
}

// ---------------------------------------------------------------------------
extern "C" void kernel_launch(void* const* d_in, const int* in_sizes, int n_in,
                              void* d_out, int out_size) {
    const float* qm  = (const float*)d_in[0];   // query  [256, 512] f32
    const float* mem = (const float*)d_in[1];   // memory [500000, 512] f32
    (void)in_sizes; (void)n_in;

    cudaFuncSetAttribute(knn_main, cudaFuncAttributeMaxDynamicSharedMemorySize, SMEM_BYTES);

    msq_kernel<<<N_MEM / 8, 256>>>(mem);            // 62500 blocks, 1 warp/row
    qsq_kernel<<<B_Q / 8, 256>>>(qm);               // 32 blocks
    knn_main<<<NSPLIT, 256, SMEM_BYTES>>>(qm, mem); // 977 blocks
    knn_merge<<<B_Q, 32>>>((float*)d_out, out_size);
}